// round 7
// baseline (speedup 1.0000x reference)
#include <cuda_runtime.h>
#include <cuda_bf16.h>

// Fused GenderAwareCrossEntropyLoss.
// 3-stage cp.async ring, ONE barrier per tile, compile-time buffer indices.
// d_in[0] logits f32 [N,7]; d_in[1] class_weights f32 [7];
// d_in[2] labels i32 [N];  d_in[3] gender i32 [N,2].
// d_out f32[1] = mean(weighted CE + gender penalty).

#define NCLS 7
#define BLOCK 512
#define TILE_ROWS 512
#define TILE_FLOATS (TILE_ROWS * NCLS)       // 3584 floats = 14336 B / buffer
#define TILE_F4 (TILE_FLOATS / 4)            // 896
#define GRID_BLOCKS (148 * 4)

__device__ double       g_accum = 0.0;
__device__ unsigned int g_count = 0u;

__device__ __forceinline__ unsigned smem_u32(const void* p) {
    return (unsigned)__cvta_generic_to_shared(p);
}
__device__ __forceinline__ void cp16(unsigned dst, const void* src) {
    asm volatile("cp.async.cg.shared.global [%0], [%1], 16;\n" :: "r"(dst), "l"(src));
}
__device__ __forceinline__ void cp_commit() {
    asm volatile("cp.async.commit_group;\n" ::: "memory");
}
template <int N>
__device__ __forceinline__ void cp_wait() {
    asm volatile("cp.async.wait_group %0;\n" :: "n"(N) : "memory");
}

__global__ void __launch_bounds__(BLOCK, 4)
gender_ce_kernel(const float* __restrict__ logits,
                 const float* __restrict__ cw,
                 const int*   __restrict__ labels,
                 const int*   __restrict__ gender,
                 float* __restrict__ out,
                 int nrows)
{
    __shared__ float s[3][TILE_FLOATS];      // 3 x 14 KB = 42 KB
    __shared__ float scw[8];

    const int t         = threadIdx.x;
    const int G         = gridDim.x;
    const int nTiles    = (nrows + TILE_ROWS - 1) / TILE_ROWS;
    const int fullTiles = nrows / TILE_ROWS;
    const long long totalF4 = (long long)nrows * NCLS / 4;
    const long long stepF4  = (long long)G * TILE_F4;

    if (t < NCLS) scw[t] = cw[t];

    // per-thread staging source pointer, advanced once per staged tile
    const float4* gsp = reinterpret_cast<const float4*>(logits)
                      + (long long)blockIdx.x * TILE_F4 + t;

    // stage tile 'st' (gsp must point at it) into buffer BN; always commits
#define STAGE(BN, st) do {                                                    \
        if ((st) < fullTiles) {                                               \
            unsigned d = smem_u32(s[BN]) + 16u * t;                           \
            cp16(d, gsp);                                                     \
            if (t < TILE_F4 - BLOCK) cp16(d + 16u * BLOCK, gsp + BLOCK);      \
        } else if ((st) < nTiles) {                                           \
            long long base = (long long)(st) * TILE_F4;                       \
            unsigned d = smem_u32(s[BN]) + 16u * t;                           \
            if (base + t < totalF4) cp16(d, gsp);                             \
            if (t < TILE_F4 - BLOCK && base + t + BLOCK < totalF4)            \
                cp16(d + 16u * BLOCK, gsp + BLOCK);                           \
        }                                                                     \
        cp_commit();                                                          \
    } while (0)

    // compute the row owned by this thread in tile 'tile' from buffer B
#define COMPUTE(B) do {                                                       \
        const int grow = tile * TILE_ROWS + t;                                \
        if (grow < nrows) {                                                   \
            const float* x = s[B] + t * NCLS;                                 \
            const float x0 = x[0], x1 = x[1], x2 = x[2], x3 = x[3],           \
                        x4 = x[4], x5 = x[5], x6 = x[6];                      \
            const float mA = fmaxf(x1, x4);                                   \
            const float mB = fmaxf(x0, fmaxf(x3, x6));                        \
            const float mC = fmaxf(x2, x5);                                   \
            const float mall = fmaxf(mA, fmaxf(mB, mC));                      \
            const int  lb = labels[grow];                                     \
            const int2 g  = reinterpret_cast<const int2*>(gender)[grow];      \
            const int gidx = (g.x << 1) | g.y;                                \
            const float mval = (gidx == 0) ? mA : ((gidx == 3) ? mC : mB);    \
            const float pen  = (mall > mval) ? 5.0f : 0.0f;                   \
            const float e01 = __expf(x0) + __expf(x1);                        \
            const float e23 = __expf(x2) + __expf(x3);                        \
            const float e45 = __expf(x4) + __expf(x5);                        \
            const float sum = (e01 + e23) + (e45 + __expf(x6));               \
            local += scw[lb] * (__logf(sum) - x[lb]) + pen;                   \
        }                                                                     \
    } while (0)

    // body: stage tile+G into BN, wait for current tile, ONE barrier, compute from B
#define BODY(B, BN)                                                           \
        STAGE(BN, tile + G);                                                  \
        gsp += stepF4;                                                        \
        cp_wait<1>();                                                         \
        __syncthreads();                                                      \
        COMPUTE(B);                                                           \
        tile += G;                                                            \
        if (tile >= nTiles) break;

    float local = 0.0f;
    int tile = blockIdx.x;

    if (tile < nTiles) {
        STAGE(0, tile);          // prologue: tile -> buf0
        gsp += stepF4;           // gsp now at tile+G

        while (true) {
            BODY(0, 1)
            BODY(1, 2)
            BODY(2, 0)
        }
    }
#undef BODY
#undef COMPUTE
#undef STAGE

    // ---- block reduction ----
    #pragma unroll
    for (int off = 16; off > 0; off >>= 1)
        local += __shfl_down_sync(0xffffffffu, local, off);

    __shared__ float swarp[BLOCK / 32];
    const int lane = t & 31;
    const int wid  = t >> 5;
    if (lane == 0) swarp[wid] = local;
    __syncthreads();

    if (wid == 0) {
        float b = (lane < BLOCK / 32) ? swarp[lane] : 0.0f;
        #pragma unroll
        for (int off = 8; off > 0; off >>= 1)
            b += __shfl_down_sync(0xffffffffu, b, off);
        if (lane == 0) {
            atomicAdd(&g_accum, (double)b);
            __threadfence();
            unsigned int ticket = atomicAdd(&g_count, 1u);
            if (ticket == gridDim.x - 1) {
                out[0] = (float)(g_accum / (double)nrows);
                g_accum = 0.0;
                g_count = 0u;
            }
        }
    }
}

extern "C" void kernel_launch(void* const* d_in, const int* in_sizes, int n_in,
                              void* d_out, int out_size)
{
    const float* logits = (const float*)d_in[0];
    const float* cw     = (const float*)d_in[1];
    const int*   labels = (const int*)d_in[2];
    const int*   gender = (const int*)d_in[3];
    float* out = (float*)d_out;

    const int nrows  = in_sizes[0] / NCLS;
    const int nTiles = (nrows + TILE_ROWS - 1) / TILE_ROWS;
    const int grid   = nTiles < GRID_BLOCKS ? nTiles : GRID_BLOCKS;

    gender_ce_kernel<<<grid, BLOCK>>>(logits, cw, labels, gender, out, nrows);
}